// round 9
// baseline (speedup 1.0000x reference)
#include <cuda_runtime.h>
#include <cuda_bf16.h>
#include <math.h>
#include <stdint.h>

#define N_NODES 100000
#define NPAD    100096      // multiple of 128
#define NE      1600000
#define HID     256

// ---------------- scratch (device globals: no allocation allowed) ----------------
__device__ __nv_bfloat16 g_hA[(size_t)NPAD * HID];
__device__ __nv_bfloat16 g_hB[(size_t)NPAD * HID];
__device__ __nv_bfloat16 g_mean[(size_t)NPAD * HID];
__device__ float g_P[(size_t)NPAD * HID];       // fp32 partial: h @ Wr + bias
__device__ __nv_bfloat16 g_wb[8 * HID * HID];   // pre-converted bf16 weights
__device__ float g_h0[NPAD * 3];
__device__ float g_mean0[NPAD * 3];
__device__ int   g_deg[N_NODES];
__device__ int   g_cursor[N_NODES];
__device__ int   g_off[N_NODES + 1];
__device__ int   g_csr[NE];
__device__ float g_part[11 * 64];
__device__ float g_scal[8];
__device__ int   g_i64flag;

// ---------------- init / dtype sniff ----------------
__global__ void k_zero() {
    int i = blockIdx.x * blockDim.x + threadIdx.x;
    if (i < N_NODES) { g_deg[i] = 0; g_cursor[i] = 0; }
    if (i == 0) g_i64flag = 1;
}

__global__ void k_detect(const unsigned int* __restrict__ w) {
    int t = threadIdx.x;
    for (int i = t; i < 1024; i += 256) {
        if (w[2 * i + 1] != 0u) g_i64flag = 0;
    }
}

// ---------------- weight conversion fp32 -> bf16 ----------------
__global__ void k_wconv(const float* w0, const float* w1, const float* w2, const float* w3,
                        const float* w4, const float* w5, const float* w6, const float* w7) {
    const float* ws[8] = {w0, w1, w2, w3, w4, w5, w6, w7};
    int i = blockIdx.x * blockDim.x + threadIdx.x;
    int m = blockIdx.y;
    g_wb[m * (HID * HID) + i] = __float2bfloat16(ws[m][i]);
}

// ---------------- normalize: reductions (warp-shuffle) ----------------
__device__ __forceinline__ float wred(float v, int op) {
    #pragma unroll
    for (int o = 16; o > 0; o >>= 1) {
        float t = __shfl_xor_sync(0xffffffff, v, o);
        v = (op == 0) ? fmaxf(v, t) : (op == 1) ? fminf(v, t) : (v + t);
    }
    return v;
}
__constant__ int c_ops[11] = {0, 1, 0, 1, 2, 2, 0, 0, 2, 2, 0};

__global__ void k_reduce1(const float* __restrict__ x) {
    __shared__ float sh[8][11];
    const float th = 1.5707964f;
    float ct = cosf(th), st = sinf(th);
    float v[11];
    v[0] = -1e30f; v[1] = 1e30f; v[2] = -1e30f; v[3] = 1e30f;
    v[4] = 0.f; v[5] = 0.f; v[6] = -1e30f; v[7] = -1e30f;
    v[8] = 0.f; v[9] = 0.f; v[10] = -1e30f;
    for (int i = blockIdx.x * blockDim.x + threadIdx.x; i < N_NODES; i += gridDim.x * blockDim.x) {
        float cx = x[i * 3 + 0], cy = x[i * 3 + 1], a = x[i * 3 + 2];
        float rx = ct * cx - st * cy, ry = st * cx + ct * cy;
        v[0] = fmaxf(v[0], cx); v[1] = fminf(v[1], cx);
        v[2] = fmaxf(v[2], cy); v[3] = fminf(v[3], cy);
        v[4] += cx; v[5] += cy;
        v[6] = fmaxf(v[6], rx); v[7] = fmaxf(v[7], ry);
        v[8] += rx; v[9] += ry;
        v[10] = fmaxf(v[10], a);
    }
    int warp = threadIdx.x >> 5, lane = threadIdx.x & 31;
    #pragma unroll
    for (int k = 0; k < 11; k++) {
        float r = wred(v[k], c_ops[k]);
        if (lane == 0) sh[warp][k] = r;
    }
    __syncthreads();
    if (threadIdx.x < 11) {
        int k = threadIdx.x, op = c_ops[k];
        float r = sh[0][k];
        #pragma unroll
        for (int w = 1; w < 8; w++) {
            float t = sh[w][k];
            r = (op == 0) ? fmaxf(r, t) : (op == 1) ? fminf(r, t) : (r + t);
        }
        g_part[k * 64 + blockIdx.x] = r;
    }
}

__global__ void k_reduce2() {
    __shared__ float res[11];
    int warp = threadIdx.x >> 5, lane = threadIdx.x & 31;
    if (warp < 11) {
        int op = c_ops[warp];
        float v = (op == 0) ? -1e30f : (op == 1) ? 1e30f : 0.f;
        #pragma unroll
        for (int i = 0; i < 2; i++) {
            float t = g_part[warp * 64 + lane + i * 32];
            v = (op == 0) ? fmaxf(v, t) : (op == 1) ? fminf(v, t) : (v + t);
        }
        v = wred(v, op);
        if (lane == 0) res[warp] = v;
    }
    __syncthreads();
    if (threadIdx.x == 0) {
        bool cond = (res[2] - res[3]) > (res[0] - res[1]);
        float m0 = (cond ? res[8] : res[4]) / (float)N_NODES;
        float m1 = (cond ? res[9] : res[5]) / (float)N_NODES;
        float d0 = cond ? res[6] : res[0];
        float d1 = cond ? res[7] : res[2];
        g_scal[0] = cond ? 1.f : 0.f;
        g_scal[1] = m0; g_scal[2] = m1;
        g_scal[3] = d0; g_scal[4] = d1;
        g_scal[5] = res[10];
    }
}

__global__ void k_normalize(const float* __restrict__ x) {
    int i = blockIdx.x * blockDim.x + threadIdx.x;
    if (i >= N_NODES) return;
    const float th = 1.5707964f;
    float ct = cosf(th), st = sinf(th);
    float cx = x[i * 3 + 0], cy = x[i * 3 + 1], a = x[i * 3 + 2];
    bool cond = g_scal[0] != 0.f;
    float ox = cond ? (ct * cx - st * cy) : cx;
    float oy = cond ? (st * cx + ct * cy) : cy;
    g_h0[i * 3 + 0] = (ox - g_scal[1]) / g_scal[3];
    g_h0[i * 3 + 1] = (oy - g_scal[2]) / g_scal[4];
    g_h0[i * 3 + 2] = a / g_scal[5];
}

// ---------------- CSR build ----------------
__device__ __forceinline__ int edge_at(const void* ei, long long idx) {
    if (g_i64flag) return (int)((const long long*)ei)[idx];
    return ((const int*)ei)[idx];
}

__global__ void k_count(const void* __restrict__ ei) {
    int e = blockIdx.x * blockDim.x + threadIdx.x;
    if (e >= NE) return;
    int dst = edge_at(ei, (long long)NE + e);
    atomicAdd(&g_deg[dst], 1);
}

__global__ void k_scan() {
    __shared__ int sh[1024];
    int tid = threadIdx.x;
    const int per = (N_NODES + 1023) / 1024;
    int start = tid * per;
    int end = start + per; if (end > N_NODES) end = N_NODES; if (start > N_NODES) start = N_NODES;
    int s = 0;
    for (int i = start; i < end; i++) s += g_deg[i];
    sh[tid] = s;
    __syncthreads();
    for (int d = 1; d < 1024; d <<= 1) {
        int v = sh[tid];
        int add = (tid >= d) ? sh[tid - d] : 0;
        __syncthreads();
        sh[tid] = v + add;
        __syncthreads();
    }
    int run = sh[tid] - s;
    for (int i = start; i < end; i++) { g_off[i] = run; run += g_deg[i]; }
    if (tid == 0) g_off[N_NODES] = NE;
}

__global__ void k_fill(const void* __restrict__ ei) {
    int e = blockIdx.x * blockDim.x + threadIdx.x;
    if (e >= NE) return;
    int src = edge_at(ei, e);
    int dst = edge_at(ei, (long long)NE + e);
    int p = atomicAdd(&g_cursor[dst], 1);
    g_csr[g_off[dst] + p] = src;
}

// ---------------- layer 1 (3-dim features) ----------------
__global__ void k_agg1() {
    int i = blockIdx.x * blockDim.x + threadIdx.x;
    if (i >= N_NODES) return;
    int s = g_off[i], e = g_off[i + 1];
    float a0 = 0.f, a1 = 0.f, a2 = 0.f;
    for (int p = s; p < e; p++) {
        int src = g_csr[p];
        a0 += g_h0[src * 3 + 0];
        a1 += g_h0[src * 3 + 1];
        a2 += g_h0[src * 3 + 2];
    }
    float c = fmaxf((float)(e - s), 1.f);
    g_mean0[i * 3 + 0] = a0 / c;
    g_mean0[i * 3 + 1] = a1 / c;
    g_mean0[i * 3 + 2] = a2 / c;
}

__global__ void k_dense1(const float* __restrict__ w1l, const float* __restrict__ b1,
                         const float* __restrict__ w1r) {
    int t = blockIdx.x * blockDim.x + threadIdx.x;
    if (t >= N_NODES * HID) return;
    int i = t >> 8, j = t & 255;
    float acc = b1[j];
    #pragma unroll
    for (int k = 0; k < 3; k++)
        acc += g_mean0[i * 3 + k] * w1l[k * HID + j] + g_h0[i * 3 + k] * w1r[k * HID + j];
    g_hA[(size_t)i * HID + j] = __float2bfloat16(tanhf(acc));
}

// ---------------- mean aggregation, HID=256 bf16 (warp per node, unroll 4) ----------------
__global__ void k_agg_bf(const __nv_bfloat16* __restrict__ h, __nv_bfloat16* __restrict__ mean) {
    int gw = (blockIdx.x * blockDim.x + threadIdx.x) >> 5;
    int lane = threadIdx.x & 31;
    if (gw >= N_NODES) return;
    int s = g_off[gw], e = g_off[gw + 1];
    float acc[8];
    #pragma unroll
    for (int j = 0; j < 8; j++) acc[j] = 0.f;

    int p = s;
    for (; p + 4 <= e; p += 4) {
        int s0 = g_csr[p], s1 = g_csr[p + 1], s2 = g_csr[p + 2], s3 = g_csr[p + 3];
        uint4 v0 = ((const uint4*)(h + (size_t)s0 * HID))[lane];
        uint4 v1 = ((const uint4*)(h + (size_t)s1 * HID))[lane];
        uint4 v2 = ((const uint4*)(h + (size_t)s2 * HID))[lane];
        uint4 v3 = ((const uint4*)(h + (size_t)s3 * HID))[lane];
        const uint4* vv[4] = {&v0, &v1, &v2, &v3};
        #pragma unroll
        for (int q = 0; q < 4; q++) {
            const __nv_bfloat162* pv = (const __nv_bfloat162*)vv[q];
            #pragma unroll
            for (int j = 0; j < 4; j++) {
                float2 f = __bfloat1622float2(pv[j]);
                acc[2 * j] += f.x;
                acc[2 * j + 1] += f.y;
            }
        }
    }
    for (; p < e; p++) {
        int src = g_csr[p];
        uint4 v = ((const uint4*)(h + (size_t)src * HID))[lane];
        const __nv_bfloat162* pv = (const __nv_bfloat162*)&v;
        #pragma unroll
        for (int j = 0; j < 4; j++) {
            float2 f = __bfloat1622float2(pv[j]);
            acc[2 * j] += f.x;
            acc[2 * j + 1] += f.y;
        }
    }
    float c = fmaxf((float)(e - s), 1.f);
    uint4 o;
    __nv_bfloat162* po = (__nv_bfloat162*)&o;
    #pragma unroll
    for (int j = 0; j < 4; j++)
        po[j] = __float22bfloat162_rn(make_float2(acc[2 * j] / c, acc[2 * j + 1] / c));
    ((uint4*)(mean + (size_t)gw * HID))[lane] = o;
}

// ---------------- bf16 tensor-core GEMM + flexible epilogue (R6 config) ----------------
// mode 0: out = tanh(acc + bias)            (bf16)
// mode 1: P   = acc + bias                  (fp32, no tanh, 'out' unused)
// mode 2: out = tanh(acc + P)               (bf16; P already contains bias)
__device__ __forceinline__ uint32_t smem_u32(const void* p) {
    return (uint32_t)__cvta_generic_to_shared(p);
}

#define GA_STRIDE 72
#define GB_STRIDE 136
#define GA_BYTES  (128 * GA_STRIDE * 2)           // 18432 per buffer
#define GB_BYTES  (64 * GB_STRIDE * 2)            // 17408 per buffer
#define G_SMEM    (2 * GA_BYTES + 2 * GB_BYTES)   // 71680

__global__ void __launch_bounds__(256) k_gemm_bf(
    const __nv_bfloat16* __restrict__ A0, const __nv_bfloat16* __restrict__ B0,
    const __nv_bfloat16* __restrict__ A1, const __nv_bfloat16* __restrict__ B1,
    const float* __restrict__ bias, __nv_bfloat16* __restrict__ out, int nA,
    int mode, float* __restrict__ P)
{
    extern __shared__ __align__(16) char sm[];
    __nv_bfloat16* Asm = (__nv_bfloat16*)sm;                      // [2][128][72]
    __nv_bfloat16* Bsm = (__nv_bfloat16*)(sm + 2 * GA_BYTES);     // [2][64][136]

    int tid  = threadIdx.x;
    int lane = tid & 31;
    int warp = tid >> 5;
    int warpRow = warp >> 2;
    int warpCol = warp & 3;
    int quad = lane >> 2;
    int tq   = lane & 3;

    int rowBase = blockIdx.x * 128;
    int colBase = blockIdx.y * 128;

    float acc[4][4][4];
    #pragma unroll
    for (int mi = 0; mi < 4; mi++)
        #pragma unroll
        for (int ni = 0; ni < 4; ni++)
            #pragma unroll
            for (int c = 0; c < 4; c++) acc[mi][ni][c] = 0.f;

    const int iters = nA * 4;

    auto issue = [&](int it, int buf) {
        int pass = it >> 2;
        int k0 = (it & 3) * 64;
        const __nv_bfloat16* A = pass ? A1 : A0;
        const __nv_bfloat16* B = pass ? B1 : B0;
        __nv_bfloat16* Ab = Asm + buf * (GA_BYTES / 2);
        __nv_bfloat16* Bb = Bsm + buf * (GB_BYTES / 2);
        #pragma unroll
        for (int i = 0; i < 4; i++) {
            int s = tid + i * 256;
            int row = s >> 3, seg = s & 7;
            const void* src = A + (size_t)(rowBase + row) * 256 + k0 + seg * 8;
            uint32_t dst = smem_u32(Ab + row * GA_STRIDE + seg * 8);
            asm volatile("cp.async.ca.shared.global [%0], [%1], 16;\n" :: "r"(dst), "l"(src));
        }
        #pragma unroll
        for (int i = 0; i < 4; i++) {
            int s = tid + i * 256;
            int row = s >> 4, seg = s & 15;
            const void* src = B + (size_t)(k0 + row) * 256 + colBase + seg * 8;
            uint32_t dst = smem_u32(Bb + row * GB_STRIDE + seg * 8);
            asm volatile("cp.async.ca.shared.global [%0], [%1], 16;\n" :: "r"(dst), "l"(src));
        }
        asm volatile("cp.async.commit_group;\n");
    };

    issue(0, 0);
    for (int it = 0; it < iters; it++) {
        int buf = it & 1;
        if (it + 1 < iters) {
            issue(it + 1, buf ^ 1);
            asm volatile("cp.async.wait_group 1;\n");
        } else {
            asm volatile("cp.async.wait_group 0;\n");
        }
        __syncthreads();

        __nv_bfloat16* Ab = Asm + buf * (GA_BYTES / 2);
        __nv_bfloat16* Bb = Bsm + buf * (GB_BYTES / 2);
        #pragma unroll
        for (int kk = 0; kk < 64; kk += 16) {
            uint32_t af[4][4];
            uint32_t bf[4][2];
            #pragma unroll
            for (int mi = 0; mi < 4; mi++) {
                int r0 = warpRow * 64 + mi * 16;
                uint32_t addr = smem_u32(Ab + (r0 + (lane & 15)) * GA_STRIDE + kk + (lane >> 4) * 8);
                asm volatile("ldmatrix.sync.aligned.m8n8.x4.shared.b16 {%0,%1,%2,%3}, [%4];"
                             : "=r"(af[mi][0]), "=r"(af[mi][1]), "=r"(af[mi][2]), "=r"(af[mi][3])
                             : "r"(addr));
            }
            #pragma unroll
            for (int nb = 0; nb < 2; nb++) {
                int n0 = warpCol * 32 + nb * 16;
                uint32_t addr = smem_u32(Bb + (kk + (lane & 15)) * GB_STRIDE + n0 + (lane >> 4) * 8);
                asm volatile("ldmatrix.sync.aligned.m8n8.x4.trans.shared.b16 {%0,%1,%2,%3}, [%4];"
                             : "=r"(bf[nb * 2][0]), "=r"(bf[nb * 2][1]),
                               "=r"(bf[nb * 2 + 1][0]), "=r"(bf[nb * 2 + 1][1])
                             : "r"(addr));
            }
            #pragma unroll
            for (int mi = 0; mi < 4; mi++)
                #pragma unroll
                for (int ni = 0; ni < 4; ni++) {
                    asm volatile(
                        "mma.sync.aligned.m16n8k16.row.col.f32.bf16.bf16.f32 "
                        "{%0,%1,%2,%3}, {%4,%5,%6,%7}, {%8,%9}, {%0,%1,%2,%3};"
                        : "+f"(acc[mi][ni][0]), "+f"(acc[mi][ni][1]),
                          "+f"(acc[mi][ni][2]), "+f"(acc[mi][ni][3])
                        : "r"(af[mi][0]), "r"(af[mi][1]), "r"(af[mi][2]), "r"(af[mi][3]),
                          "r"(bf[ni][0]), "r"(bf[ni][1]));
                }
        }
        __syncthreads();
    }

    // epilogue
    #pragma unroll
    for (int ni = 0; ni < 4; ni++) {
        int col = colBase + warpCol * 32 + ni * 8 + tq * 2;
        float b0 = bias[col], b1 = bias[col + 1];
        #pragma unroll
        for (int mi = 0; mi < 4; mi++) {
            int r0 = rowBase + warpRow * 64 + mi * 16 + quad;
            int r1 = r0 + 8;
            if (mode == 0) {
                if (r0 < N_NODES) {
                    __nv_bfloat162 v = __float22bfloat162_rn(
                        make_float2(tanhf(acc[mi][ni][0] + b0), tanhf(acc[mi][ni][1] + b1)));
                    *(__nv_bfloat162*)(out + (size_t)r0 * 256 + col) = v;
                }
                if (r1 < N_NODES) {
                    __nv_bfloat162 v = __float22bfloat162_rn(
                        make_float2(tanhf(acc[mi][ni][2] + b0), tanhf(acc[mi][ni][3] + b1)));
                    *(__nv_bfloat162*)(out + (size_t)r1 * 256 + col) = v;
                }
            } else if (mode == 1) {
                if (r0 < N_NODES)
                    *(float2*)(P + (size_t)r0 * 256 + col) =
                        make_float2(acc[mi][ni][0] + b0, acc[mi][ni][1] + b1);
                if (r1 < N_NODES)
                    *(float2*)(P + (size_t)r1 * 256 + col) =
                        make_float2(acc[mi][ni][2] + b0, acc[mi][ni][3] + b1);
            } else {
                if (r0 < N_NODES) {
                    float2 p = *(const float2*)(P + (size_t)r0 * 256 + col);
                    __nv_bfloat162 v = __float22bfloat162_rn(
                        make_float2(tanhf(acc[mi][ni][0] + p.x), tanhf(acc[mi][ni][1] + p.y)));
                    *(__nv_bfloat162*)(out + (size_t)r0 * 256 + col) = v;
                }
                if (r1 < N_NODES) {
                    float2 p = *(const float2*)(P + (size_t)r1 * 256 + col);
                    __nv_bfloat162 v = __float22bfloat162_rn(
                        make_float2(tanhf(acc[mi][ni][2] + p.x), tanhf(acc[mi][ni][3] + p.y)));
                    *(__nv_bfloat162*)(out + (size_t)r1 * 256 + col) = v;
                }
            }
        }
    }
}

// ---------------- final projection (256->4) + softmax, warp per node ----------------
__global__ void k_last(const __nv_bfloat16* __restrict__ h, const float* __restrict__ wlast,
                       const float* __restrict__ blast, float* __restrict__ out) {
    int gw = (blockIdx.x * blockDim.x + threadIdx.x) >> 5;
    int lane = threadIdx.x & 31;
    if (gw >= N_NODES) return;
    uint4 v = ((const uint4*)(h + (size_t)gw * 256))[lane];
    const __nv_bfloat162* pv = (const __nv_bfloat162*)&v;
    float hv[8];
    #pragma unroll
    for (int j = 0; j < 4; j++) {
        float2 f = __bfloat1622float2(pv[j]);
        hv[2 * j] = f.x;
        hv[2 * j + 1] = f.y;
    }
    float acc0 = 0.f, acc1 = 0.f, acc2 = 0.f, acc3 = 0.f;
    #pragma unroll
    for (int t = 0; t < 8; t++) {
        int k = lane * 8 + t;
        float4 wl = ((const float4*)wlast)[k];
        acc0 += hv[t] * wl.x;
        acc1 += hv[t] * wl.y;
        acc2 += hv[t] * wl.z;
        acc3 += hv[t] * wl.w;
    }
    #pragma unroll
    for (int o = 16; o > 0; o >>= 1) {
        acc0 += __shfl_xor_sync(0xffffffff, acc0, o);
        acc1 += __shfl_xor_sync(0xffffffff, acc1, o);
        acc2 += __shfl_xor_sync(0xffffffff, acc2, o);
        acc3 += __shfl_xor_sync(0xffffffff, acc3, o);
    }
    if (lane == 0) {
        float l0 = acc0 + blast[0], l1 = acc1 + blast[1];
        float l2 = acc2 + blast[2], l3 = acc3 + blast[3];
        float m = fmaxf(fmaxf(l0, l1), fmaxf(l2, l3));
        float e0 = expf(l0 - m), e1 = expf(l1 - m), e2 = expf(l2 - m), e3 = expf(l3 - m);
        float s = e0 + e1 + e2 + e3;
        out[gw * 4 + 0] = e0 / s;
        out[gw * 4 + 1] = e1 / s;
        out[gw * 4 + 2] = e2 / s;
        out[gw * 4 + 3] = e3 / s;
    }
}

// ---------------- host ----------------
extern "C" void kernel_launch(void* const* d_in, const int* in_sizes, int n_in,
                              void* d_out, int out_size) {
    const float* x    = (const float*)d_in[0];
    const void*  ei   = d_in[1];
    const float* w1l  = (const float*)d_in[2];
    const float* b1   = (const float*)d_in[3];
    const float* w1r  = (const float*)d_in[4];
    const float* w2l  = (const float*)d_in[5];
    const float* b2   = (const float*)d_in[6];
    const float* w2r  = (const float*)d_in[7];
    const float* w3l  = (const float*)d_in[8];
    const float* b3   = (const float*)d_in[9];
    const float* w3r  = (const float*)d_in[10];
    const float* w4l  = (const float*)d_in[11];
    const float* b4   = (const float*)d_in[12];
    const float* w4r  = (const float*)d_in[13];
    const float* wl1  = (const float*)d_in[14];
    const float* bl1  = (const float*)d_in[15];
    const float* wl2  = (const float*)d_in[16];
    const float* bl2  = (const float*)d_in[17];
    const float* wlast = (const float*)d_in[18];
    const float* blast = (const float*)d_in[19];
    float* out = (float*)d_out;

    static __nv_bfloat16 *hA = nullptr, *hB = nullptr, *mean = nullptr, *wb = nullptr;
    static float* P = nullptr;
    static cudaStream_t side = nullptr;
    static cudaEvent_t evF = nullptr, evJ = nullptr;
    if (!hA) {
        cudaGetSymbolAddress((void**)&hA, g_hA);
        cudaGetSymbolAddress((void**)&hB, g_hB);
        cudaGetSymbolAddress((void**)&mean, g_mean);
        cudaGetSymbolAddress((void**)&wb, g_wb);
        cudaGetSymbolAddress((void**)&P, g_P);
        cudaFuncSetAttribute(k_gemm_bf, cudaFuncAttributeMaxDynamicSharedMemorySize, G_SMEM);
        cudaStreamCreateWithFlags(&side, cudaStreamNonBlocking);
        cudaEventCreateWithFlags(&evF, cudaEventDisableTiming);
        cudaEventCreateWithFlags(&evJ, cudaEventDisableTiming);
    }
    const int WSZ = HID * HID;
    const __nv_bfloat16* bw2l = wb + 0 * WSZ;
    const __nv_bfloat16* bw2r = wb + 1 * WSZ;
    const __nv_bfloat16* bw3l = wb + 2 * WSZ;
    const __nv_bfloat16* bw3r = wb + 3 * WSZ;
    const __nv_bfloat16* bw4l = wb + 4 * WSZ;
    const __nv_bfloat16* bw4r = wb + 5 * WSZ;
    const __nv_bfloat16* bwl1 = wb + 6 * WSZ;
    const __nv_bfloat16* bwl2 = wb + 7 * WSZ;

    const int TB = 256;
    const int aggBlocks = (N_NODES * 32 + TB - 1) / TB;
    dim3 ggrid(NPAD / 128, 2);

    // ---- setup: CSR build (main) ∥ normalize chain + wconv (side) ----
    k_zero<<<(N_NODES + TB - 1) / TB, TB>>>();
    k_detect<<<1, 256>>>((const unsigned int*)ei);
    cudaEventRecord(evF, 0);
    cudaStreamWaitEvent(side, evF, 0);
    k_wconv<<<dim3(WSZ / TB, 8), TB, 0, side>>>(w2l, w2r, w3l, w3r, w4l, w4r, wl1, wl2);
    k_reduce1<<<64, 256, 0, side>>>(x);
    k_reduce2<<<1, 352, 0, side>>>();
    k_normalize<<<(N_NODES + TB - 1) / TB, TB, 0, side>>>(x);
    cudaEventRecord(evJ, side);
    k_count<<<(NE + TB - 1) / TB, TB>>>(ei);
    k_scan<<<1, 1024>>>();
    k_fill<<<(NE + TB - 1) / TB, TB>>>(ei);
    cudaStreamWaitEvent(0, evJ, 0);

    // layer 1 (K=3)
    k_agg1<<<(N_NODES + TB - 1) / TB, TB>>>();
    k_dense1<<<(N_NODES * HID + TB - 1) / TB, TB>>>(w1l, b1, w1r);

    // ---- SAGE layer macro: [agg(h) ∥ P = h@Wr + b] ; out = tanh(mean@Wl + P) ----
    auto sage = [&](const __nv_bfloat16* hin, const __nv_bfloat16* wlB, const __nv_bfloat16* wrB,
                    const float* bias, __nv_bfloat16* hout) {
        cudaEventRecord(evF, 0);
        cudaStreamWaitEvent(side, evF, 0);
        k_gemm_bf<<<ggrid, 256, G_SMEM, side>>>(hin, wrB, hin, wrB, bias, hout, 1, 1, P);
        cudaEventRecord(evJ, side);
        k_agg_bf<<<aggBlocks, TB>>>(hin, mean);
        cudaStreamWaitEvent(0, evJ, 0);
        k_gemm_bf<<<ggrid, 256, G_SMEM>>>(mean, wlB, mean, wlB, bias, hout, 1, 2, P);
    };

    sage(hA, bw2l, bw2r, b2, hB);   // layer 2
    sage(hB, bw3l, bw3r, b3, hA);   // layer 3
    sage(hA, bw4l, bw4r, b4, hB);   // layer 4

    // MLP
    k_gemm_bf<<<ggrid, 256, G_SMEM>>>(hB, bwl1, hB, bwl1, bl1, hA, 1, 0, P);
    k_gemm_bf<<<ggrid, 256, G_SMEM>>>(hA, bwl2, hA, bwl2, bl2, hB, 1, 0, P);

    // final linear + softmax
    k_last<<<aggBlocks, TB>>>(hB, wlast, blast, out);
}

// round 10
// speedup vs baseline: 1.2719x; 1.2719x over previous
#include <cuda_runtime.h>
#include <cuda_bf16.h>
#include <math.h>
#include <stdint.h>

#define N_NODES 100000
#define NPAD    100096      // multiple of 128
#define NE      1600000
#define HID     256

// ---------------- scratch (device globals: no allocation allowed) ----------------
__device__ __nv_bfloat16 g_hA[(size_t)NPAD * HID];
__device__ __nv_bfloat16 g_hB[(size_t)NPAD * HID];
__device__ __nv_bfloat16 g_mean[(size_t)NPAD * HID];
__device__ __nv_bfloat16 g_wb[8 * HID * HID];   // pre-converted bf16 weights
__device__ float g_h0[NPAD * 3];
__device__ float g_mean0[NPAD * 3];
__device__ int   g_deg[N_NODES];
__device__ int   g_cursor[N_NODES];
__device__ int   g_off[N_NODES + 1];
__device__ unsigned g_csr[NE];                  // byte offsets: src * 512
__device__ float g_part[11 * 64];
__device__ float g_scal[8];
__device__ int   g_i64flag;

// ---------------- init / dtype sniff ----------------
__global__ void k_zero() {
    int i = blockIdx.x * blockDim.x + threadIdx.x;
    if (i < N_NODES) { g_deg[i] = 0; g_cursor[i] = 0; }
    if (i == 0) g_i64flag = 1;
}

__global__ void k_detect(const unsigned int* __restrict__ w) {
    int t = threadIdx.x;
    for (int i = t; i < 1024; i += 256) {
        if (w[2 * i + 1] != 0u) g_i64flag = 0;
    }
}

// ---------------- weight conversion fp32 -> bf16 ----------------
__global__ void k_wconv(const float* w0, const float* w1, const float* w2, const float* w3,
                        const float* w4, const float* w5, const float* w6, const float* w7) {
    const float* ws[8] = {w0, w1, w2, w3, w4, w5, w6, w7};
    int i = blockIdx.x * blockDim.x + threadIdx.x;
    int m = blockIdx.y;
    g_wb[m * (HID * HID) + i] = __float2bfloat16(ws[m][i]);
}

// ---------------- normalize: reductions (warp-shuffle) ----------------
__device__ __forceinline__ float wred(float v, int op) {
    #pragma unroll
    for (int o = 16; o > 0; o >>= 1) {
        float t = __shfl_xor_sync(0xffffffff, v, o);
        v = (op == 0) ? fmaxf(v, t) : (op == 1) ? fminf(v, t) : (v + t);
    }
    return v;
}
__constant__ int c_ops[11] = {0, 1, 0, 1, 2, 2, 0, 0, 2, 2, 0};

__global__ void k_reduce1(const float* __restrict__ x) {
    __shared__ float sh[8][11];
    const float th = 1.5707964f;
    float ct = cosf(th), st = sinf(th);
    float v[11];
    v[0] = -1e30f; v[1] = 1e30f; v[2] = -1e30f; v[3] = 1e30f;
    v[4] = 0.f; v[5] = 0.f; v[6] = -1e30f; v[7] = -1e30f;
    v[8] = 0.f; v[9] = 0.f; v[10] = -1e30f;
    for (int i = blockIdx.x * blockDim.x + threadIdx.x; i < N_NODES; i += gridDim.x * blockDim.x) {
        float cx = x[i * 3 + 0], cy = x[i * 3 + 1], a = x[i * 3 + 2];
        float rx = ct * cx - st * cy, ry = st * cx + ct * cy;
        v[0] = fmaxf(v[0], cx); v[1] = fminf(v[1], cx);
        v[2] = fmaxf(v[2], cy); v[3] = fminf(v[3], cy);
        v[4] += cx; v[5] += cy;
        v[6] = fmaxf(v[6], rx); v[7] = fmaxf(v[7], ry);
        v[8] += rx; v[9] += ry;
        v[10] = fmaxf(v[10], a);
    }
    int warp = threadIdx.x >> 5, lane = threadIdx.x & 31;
    #pragma unroll
    for (int k = 0; k < 11; k++) {
        float r = wred(v[k], c_ops[k]);
        if (lane == 0) sh[warp][k] = r;
    }
    __syncthreads();
    if (threadIdx.x < 11) {
        int k = threadIdx.x, op = c_ops[k];
        float r = sh[0][k];
        #pragma unroll
        for (int w = 1; w < 8; w++) {
            float t = sh[w][k];
            r = (op == 0) ? fmaxf(r, t) : (op == 1) ? fminf(r, t) : (r + t);
        }
        g_part[k * 64 + blockIdx.x] = r;
    }
}

__global__ void k_reduce2() {
    __shared__ float res[11];
    int warp = threadIdx.x >> 5, lane = threadIdx.x & 31;
    if (warp < 11) {
        int op = c_ops[warp];
        float v = (op == 0) ? -1e30f : (op == 1) ? 1e30f : 0.f;
        #pragma unroll
        for (int i = 0; i < 2; i++) {
            float t = g_part[warp * 64 + lane + i * 32];
            v = (op == 0) ? fmaxf(v, t) : (op == 1) ? fminf(v, t) : (v + t);
        }
        v = wred(v, op);
        if (lane == 0) res[warp] = v;
    }
    __syncthreads();
    if (threadIdx.x == 0) {
        bool cond = (res[2] - res[3]) > (res[0] - res[1]);
        float m0 = (cond ? res[8] : res[4]) / (float)N_NODES;
        float m1 = (cond ? res[9] : res[5]) / (float)N_NODES;
        float d0 = cond ? res[6] : res[0];
        float d1 = cond ? res[7] : res[2];
        g_scal[0] = cond ? 1.f : 0.f;
        g_scal[1] = m0; g_scal[2] = m1;
        g_scal[3] = d0; g_scal[4] = d1;
        g_scal[5] = res[10];
    }
}

__global__ void k_normalize(const float* __restrict__ x) {
    int i = blockIdx.x * blockDim.x + threadIdx.x;
    if (i >= N_NODES) return;
    const float th = 1.5707964f;
    float ct = cosf(th), st = sinf(th);
    float cx = x[i * 3 + 0], cy = x[i * 3 + 1], a = x[i * 3 + 2];
    bool cond = g_scal[0] != 0.f;
    float ox = cond ? (ct * cx - st * cy) : cx;
    float oy = cond ? (st * cx + ct * cy) : cy;
    g_h0[i * 3 + 0] = (ox - g_scal[1]) / g_scal[3];
    g_h0[i * 3 + 1] = (oy - g_scal[2]) / g_scal[4];
    g_h0[i * 3 + 2] = a / g_scal[5];
}

// ---------------- CSR build (stores byte offsets src*512) ----------------
__device__ __forceinline__ int edge_at(const void* ei, long long idx) {
    if (g_i64flag) return (int)((const long long*)ei)[idx];
    return ((const int*)ei)[idx];
}

__global__ void k_count(const void* __restrict__ ei) {
    int e = blockIdx.x * blockDim.x + threadIdx.x;
    if (e >= NE) return;
    int dst = edge_at(ei, (long long)NE + e);
    atomicAdd(&g_deg[dst], 1);
}

__global__ void k_scan() {
    __shared__ int sh[1024];
    int tid = threadIdx.x;
    const int per = (N_NODES + 1023) / 1024;
    int start = tid * per;
    int end = start + per; if (end > N_NODES) end = N_NODES; if (start > N_NODES) start = N_NODES;
    int s = 0;
    for (int i = start; i < end; i++) s += g_deg[i];
    sh[tid] = s;
    __syncthreads();
    for (int d = 1; d < 1024; d <<= 1) {
        int v = sh[tid];
        int add = (tid >= d) ? sh[tid - d] : 0;
        __syncthreads();
        sh[tid] = v + add;
        __syncthreads();
    }
    int run = sh[tid] - s;
    for (int i = start; i < end; i++) { g_off[i] = run; run += g_deg[i]; }
    if (tid == 0) g_off[N_NODES] = NE;
}

__global__ void k_fill(const void* __restrict__ ei) {
    int e = blockIdx.x * blockDim.x + threadIdx.x;
    if (e >= NE) return;
    int src = edge_at(ei, e);
    int dst = edge_at(ei, (long long)NE + e);
    int p = atomicAdd(&g_cursor[dst], 1);
    g_csr[g_off[dst] + p] = ((unsigned)src) << 9;   // byte offset into 512B rows
}

// ---------------- layer 1 (3-dim features) ----------------
__global__ void k_agg1() {
    int i = blockIdx.x * blockDim.x + threadIdx.x;
    if (i >= N_NODES) return;
    int s = g_off[i], e = g_off[i + 1];
    float a0 = 0.f, a1 = 0.f, a2 = 0.f;
    for (int p = s; p < e; p++) {
        int src = (int)(g_csr[p] >> 9);
        a0 += g_h0[src * 3 + 0];
        a1 += g_h0[src * 3 + 1];
        a2 += g_h0[src * 3 + 2];
    }
    float inv = 1.f / fmaxf((float)(e - s), 1.f);
    g_mean0[i * 3 + 0] = a0 * inv;
    g_mean0[i * 3 + 1] = a1 * inv;
    g_mean0[i * 3 + 2] = a2 * inv;
}

__global__ void k_dense1(const float* __restrict__ w1l, const float* __restrict__ b1,
                         const float* __restrict__ w1r) {
    int t = blockIdx.x * blockDim.x + threadIdx.x;
    if (t >= N_NODES * HID) return;
    int i = t >> 8, j = t & 255;
    float acc = b1[j];
    #pragma unroll
    for (int k = 0; k < 3; k++)
        acc += g_mean0[i * 3 + k] * w1l[k * HID + j] + g_h0[i * 3 + k] * w1r[k * HID + j];
    g_hA[(size_t)i * HID + j] = __float2bfloat16(tanhf(acc));
}

// ---------------- mean aggregation: warp/node, pairwise bf16 add + fp32 acc ----------------
__global__ void k_agg_bf(const __nv_bfloat16* __restrict__ h, __nv_bfloat16* __restrict__ mean) {
    int gw = (blockIdx.x * blockDim.x + threadIdx.x) >> 5;
    int lane = threadIdx.x & 31;
    if (gw >= N_NODES) return;
    int s = g_off[gw], e = g_off[gw + 1];
    const char* hb = (const char*)h;
    int laneOff = lane * 16;
    float acc[8];
    #pragma unroll
    for (int j = 0; j < 8; j++) acc[j] = 0.f;

    int p = s;
    for (; p + 4 <= e; p += 4) {
        unsigned o0 = g_csr[p], o1 = g_csr[p + 1], o2 = g_csr[p + 2], o3 = g_csr[p + 3];
        uint4 v0 = *(const uint4*)(hb + o0 + laneOff);
        uint4 v1 = *(const uint4*)(hb + o1 + laneOff);
        uint4 v2 = *(const uint4*)(hb + o2 + laneOff);
        uint4 v3 = *(const uint4*)(hb + o3 + laneOff);
        const __nv_bfloat162* a0 = (const __nv_bfloat162*)&v0;
        const __nv_bfloat162* a1 = (const __nv_bfloat162*)&v1;
        const __nv_bfloat162* a2 = (const __nv_bfloat162*)&v2;
        const __nv_bfloat162* a3 = (const __nv_bfloat162*)&v3;
        #pragma unroll
        for (int j = 0; j < 4; j++) {
            __nv_bfloat162 s01 = __hadd2(a0[j], a1[j]);   // one bf16 add per pair
            __nv_bfloat162 s23 = __hadd2(a2[j], a3[j]);
            float2 f01 = __bfloat1622float2(s01);
            float2 f23 = __bfloat1622float2(s23);
            acc[2 * j]     += f01.x + f23.x;
            acc[2 * j + 1] += f01.y + f23.y;
        }
    }
    if (p + 2 <= e) {
        unsigned o0 = g_csr[p], o1 = g_csr[p + 1];
        uint4 v0 = *(const uint4*)(hb + o0 + laneOff);
        uint4 v1 = *(const uint4*)(hb + o1 + laneOff);
        const __nv_bfloat162* a0 = (const __nv_bfloat162*)&v0;
        const __nv_bfloat162* a1 = (const __nv_bfloat162*)&v1;
        #pragma unroll
        for (int j = 0; j < 4; j++) {
            float2 f = __bfloat1622float2(__hadd2(a0[j], a1[j]));
            acc[2 * j]     += f.x;
            acc[2 * j + 1] += f.y;
        }
        p += 2;
    }
    if (p < e) {
        uint4 v = *(const uint4*)(hb + g_csr[p] + laneOff);
        const __nv_bfloat162* a = (const __nv_bfloat162*)&v;
        #pragma unroll
        for (int j = 0; j < 4; j++) {
            float2 f = __bfloat1622float2(a[j]);
            acc[2 * j]     += f.x;
            acc[2 * j + 1] += f.y;
        }
    }
    float inv = 1.f / fmaxf((float)(e - s), 1.f);
    uint4 o;
    __nv_bfloat162* po = (__nv_bfloat162*)&o;
    #pragma unroll
    for (int j = 0; j < 4; j++)
        po[j] = __float22bfloat162_rn(make_float2(acc[2 * j] * inv, acc[2 * j + 1] * inv));
    ((uint4*)(mean + (size_t)gw * HID))[lane] = o;
}

// ---------------- bf16 tensor-core fused dual-GEMM + bias + tanh (R6 config) ----------------
__device__ __forceinline__ uint32_t smem_u32(const void* p) {
    return (uint32_t)__cvta_generic_to_shared(p);
}

#define GA_STRIDE 72
#define GB_STRIDE 136
#define GA_BYTES  (128 * GA_STRIDE * 2)           // 18432 per buffer
#define GB_BYTES  (64 * GB_STRIDE * 2)            // 17408 per buffer
#define G_SMEM    (2 * GA_BYTES + 2 * GB_BYTES)   // 71680

__global__ void __launch_bounds__(256) k_gemm_bf(
    const __nv_bfloat16* __restrict__ A0, const __nv_bfloat16* __restrict__ B0,
    const __nv_bfloat16* __restrict__ A1, const __nv_bfloat16* __restrict__ B1,
    const float* __restrict__ bias, __nv_bfloat16* __restrict__ out, int nA)
{
    extern __shared__ __align__(16) char sm[];
    __nv_bfloat16* Asm = (__nv_bfloat16*)sm;
    __nv_bfloat16* Bsm = (__nv_bfloat16*)(sm + 2 * GA_BYTES);

    int tid  = threadIdx.x;
    int lane = tid & 31;
    int warp = tid >> 5;
    int warpRow = warp >> 2;
    int warpCol = warp & 3;
    int quad = lane >> 2;
    int tq   = lane & 3;

    int rowBase = blockIdx.x * 128;
    int colBase = blockIdx.y * 128;

    float acc[4][4][4];
    #pragma unroll
    for (int mi = 0; mi < 4; mi++)
        #pragma unroll
        for (int ni = 0; ni < 4; ni++)
            #pragma unroll
            for (int c = 0; c < 4; c++) acc[mi][ni][c] = 0.f;

    const int iters = nA * 4;

    auto issue = [&](int it, int buf) {
        int pass = it >> 2;
        int k0 = (it & 3) * 64;
        const __nv_bfloat16* A = pass ? A1 : A0;
        const __nv_bfloat16* B = pass ? B1 : B0;
        __nv_bfloat16* Ab = Asm + buf * (GA_BYTES / 2);
        __nv_bfloat16* Bb = Bsm + buf * (GB_BYTES / 2);
        #pragma unroll
        for (int i = 0; i < 4; i++) {
            int s = tid + i * 256;
            int row = s >> 3, seg = s & 7;
            const void* src = A + (size_t)(rowBase + row) * 256 + k0 + seg * 8;
            uint32_t dst = smem_u32(Ab + row * GA_STRIDE + seg * 8);
            asm volatile("cp.async.ca.shared.global [%0], [%1], 16;\n" :: "r"(dst), "l"(src));
        }
        #pragma unroll
        for (int i = 0; i < 4; i++) {
            int s = tid + i * 256;
            int row = s >> 4, seg = s & 15;
            const void* src = B + (size_t)(k0 + row) * 256 + colBase + seg * 8;
            uint32_t dst = smem_u32(Bb + row * GB_STRIDE + seg * 8);
            asm volatile("cp.async.ca.shared.global [%0], [%1], 16;\n" :: "r"(dst), "l"(src));
        }
        asm volatile("cp.async.commit_group;\n");
    };

    issue(0, 0);
    for (int it = 0; it < iters; it++) {
        int buf = it & 1;
        if (it + 1 < iters) {
            issue(it + 1, buf ^ 1);
            asm volatile("cp.async.wait_group 1;\n");
        } else {
            asm volatile("cp.async.wait_group 0;\n");
        }
        __syncthreads();

        __nv_bfloat16* Ab = Asm + buf * (GA_BYTES / 2);
        __nv_bfloat16* Bb = Bsm + buf * (GB_BYTES / 2);
        #pragma unroll
        for (int kk = 0; kk < 64; kk += 16) {
            uint32_t af[4][4];
            uint32_t bf[4][2];
            #pragma unroll
            for (int mi = 0; mi < 4; mi++) {
                int r0 = warpRow * 64 + mi * 16;
                uint32_t addr = smem_u32(Ab + (r0 + (lane & 15)) * GA_STRIDE + kk + (lane >> 4) * 8);
                asm volatile("ldmatrix.sync.aligned.m8n8.x4.shared.b16 {%0,%1,%2,%3}, [%4];"
                             : "=r"(af[mi][0]), "=r"(af[mi][1]), "=r"(af[mi][2]), "=r"(af[mi][3])
                             : "r"(addr));
            }
            #pragma unroll
            for (int nb = 0; nb < 2; nb++) {
                int n0 = warpCol * 32 + nb * 16;
                uint32_t addr = smem_u32(Bb + (kk + (lane & 15)) * GB_STRIDE + n0 + (lane >> 4) * 8);
                asm volatile("ldmatrix.sync.aligned.m8n8.x4.trans.shared.b16 {%0,%1,%2,%3}, [%4];"
                             : "=r"(bf[nb * 2][0]), "=r"(bf[nb * 2][1]),
                               "=r"(bf[nb * 2 + 1][0]), "=r"(bf[nb * 2 + 1][1])
                             : "r"(addr));
            }
            #pragma unroll
            for (int mi = 0; mi < 4; mi++)
                #pragma unroll
                for (int ni = 0; ni < 4; ni++) {
                    asm volatile(
                        "mma.sync.aligned.m16n8k16.row.col.f32.bf16.bf16.f32 "
                        "{%0,%1,%2,%3}, {%4,%5,%6,%7}, {%8,%9}, {%0,%1,%2,%3};"
                        : "+f"(acc[mi][ni][0]), "+f"(acc[mi][ni][1]),
                          "+f"(acc[mi][ni][2]), "+f"(acc[mi][ni][3])
                        : "r"(af[mi][0]), "r"(af[mi][1]), "r"(af[mi][2]), "r"(af[mi][3]),
                          "r"(bf[ni][0]), "r"(bf[ni][1]));
                }
        }
        __syncthreads();
    }

    // epilogue: bias + tanh, bf16 out
    #pragma unroll
    for (int ni = 0; ni < 4; ni++) {
        int col = colBase + warpCol * 32 + ni * 8 + tq * 2;
        float b0 = bias[col], b1 = bias[col + 1];
        #pragma unroll
        for (int mi = 0; mi < 4; mi++) {
            int r0 = rowBase + warpRow * 64 + mi * 16 + quad;
            if (r0 < N_NODES) {
                __nv_bfloat162 v = __float22bfloat162_rn(
                    make_float2(tanhf(acc[mi][ni][0] + b0), tanhf(acc[mi][ni][1] + b1)));
                *(__nv_bfloat162*)(out + (size_t)r0 * 256 + col) = v;
            }
            int r1 = r0 + 8;
            if (r1 < N_NODES) {
                __nv_bfloat162 v = __float22bfloat162_rn(
                    make_float2(tanhf(acc[mi][ni][2] + b0), tanhf(acc[mi][ni][3] + b1)));
                *(__nv_bfloat162*)(out + (size_t)r1 * 256 + col) = v;
            }
        }
    }
}

// ---------------- final projection (256->4) + softmax, warp per node ----------------
__global__ void k_last(const __nv_bfloat16* __restrict__ h, const float* __restrict__ wlast,
                       const float* __restrict__ blast, float* __restrict__ out) {
    int gw = (blockIdx.x * blockDim.x + threadIdx.x) >> 5;
    int lane = threadIdx.x & 31;
    if (gw >= N_NODES) return;
    uint4 v = ((const uint4*)(h + (size_t)gw * 256))[lane];
    const __nv_bfloat162* pv = (const __nv_bfloat162*)&v;
    float hv[8];
    #pragma unroll
    for (int j = 0; j < 4; j++) {
        float2 f = __bfloat1622float2(pv[j]);
        hv[2 * j] = f.x;
        hv[2 * j + 1] = f.y;
    }
    float acc0 = 0.f, acc1 = 0.f, acc2 = 0.f, acc3 = 0.f;
    #pragma unroll
    for (int t = 0; t < 8; t++) {
        int k = lane * 8 + t;
        float4 wl = ((const float4*)wlast)[k];
        acc0 += hv[t] * wl.x;
        acc1 += hv[t] * wl.y;
        acc2 += hv[t] * wl.z;
        acc3 += hv[t] * wl.w;
    }
    #pragma unroll
    for (int o = 16; o > 0; o >>= 1) {
        acc0 += __shfl_xor_sync(0xffffffff, acc0, o);
        acc1 += __shfl_xor_sync(0xffffffff, acc1, o);
        acc2 += __shfl_xor_sync(0xffffffff, acc2, o);
        acc3 += __shfl_xor_sync(0xffffffff, acc3, o);
    }
    if (lane == 0) {
        float l0 = acc0 + blast[0], l1 = acc1 + blast[1];
        float l2 = acc2 + blast[2], l3 = acc3 + blast[3];
        float m = fmaxf(fmaxf(l0, l1), fmaxf(l2, l3));
        float e0 = expf(l0 - m), e1 = expf(l1 - m), e2 = expf(l2 - m), e3 = expf(l3 - m);
        float s = e0 + e1 + e2 + e3;
        out[gw * 4 + 0] = e0 / s;
        out[gw * 4 + 1] = e1 / s;
        out[gw * 4 + 2] = e2 / s;
        out[gw * 4 + 3] = e3 / s;
    }
}

// ---------------- host ----------------
extern "C" void kernel_launch(void* const* d_in, const int* in_sizes, int n_in,
                              void* d_out, int out_size) {
    const float* x    = (const float*)d_in[0];
    const void*  ei   = d_in[1];
    const float* w1l  = (const float*)d_in[2];
    const float* b1   = (const float*)d_in[3];
    const float* w1r  = (const float*)d_in[4];
    const float* w2l  = (const float*)d_in[5];
    const float* b2   = (const float*)d_in[6];
    const float* w2r  = (const float*)d_in[7];
    const float* w3l  = (const float*)d_in[8];
    const float* b3   = (const float*)d_in[9];
    const float* w3r  = (const float*)d_in[10];
    const float* w4l  = (const float*)d_in[11];
    const float* b4   = (const float*)d_in[12];
    const float* w4r  = (const float*)d_in[13];
    const float* wl1  = (const float*)d_in[14];
    const float* bl1  = (const float*)d_in[15];
    const float* wl2  = (const float*)d_in[16];
    const float* bl2  = (const float*)d_in[17];
    const float* wlast = (const float*)d_in[18];
    const float* blast = (const float*)d_in[19];
    float* out = (float*)d_out;

    static __nv_bfloat16 *hA = nullptr, *hB = nullptr, *mean = nullptr, *wb = nullptr;
    if (!hA) {
        cudaGetSymbolAddress((void**)&hA, g_hA);
        cudaGetSymbolAddress((void**)&hB, g_hB);
        cudaGetSymbolAddress((void**)&mean, g_mean);
        cudaGetSymbolAddress((void**)&wb, g_wb);
        cudaFuncSetAttribute(k_gemm_bf, cudaFuncAttributeMaxDynamicSharedMemorySize, G_SMEM);
    }
    const int WSZ = HID * HID;
    const __nv_bfloat16* bw2l = wb + 0 * WSZ;
    const __nv_bfloat16* bw2r = wb + 1 * WSZ;
    const __nv_bfloat16* bw3l = wb + 2 * WSZ;
    const __nv_bfloat16* bw3r = wb + 3 * WSZ;
    const __nv_bfloat16* bw4l = wb + 4 * WSZ;
    const __nv_bfloat16* bw4r = wb + 5 * WSZ;
    const __nv_bfloat16* bwl1 = wb + 6 * WSZ;
    const __nv_bfloat16* bwl2 = wb + 7 * WSZ;

    const int TB = 256;
    const int aggBlocks = (N_NODES * 32 + TB - 1) / TB;
    dim3 ggrid(NPAD / 128, 2);

    k_zero<<<(N_NODES + TB - 1) / TB, TB>>>();
    k_detect<<<1, 256>>>((const unsigned int*)ei);
    k_wconv<<<dim3(WSZ / TB, 8), TB>>>(w2l, w2r, w3l, w3r, w4l, w4r, wl1, wl2);
    k_reduce1<<<64, 256>>>(x);
    k_reduce2<<<1, 352>>>();
    k_normalize<<<(N_NODES + TB - 1) / TB, TB>>>(x);
    k_count<<<(NE + TB - 1) / TB, TB>>>(ei);
    k_scan<<<1, 1024>>>();
    k_fill<<<(NE + TB - 1) / TB, TB>>>(ei);

    // layer 1 (K=3)
    k_agg1<<<(N_NODES + TB - 1) / TB, TB>>>();
    k_dense1<<<(N_NODES * HID + TB - 1) / TB, TB>>>(w1l, b1, w1r);

    // layer 2
    k_agg_bf<<<aggBlocks, TB>>>(hA, mean);
    k_gemm_bf<<<ggrid, 256, G_SMEM>>>(mean, bw2l, hA, bw2r, b2, hB, 2);
    // layer 3
    k_agg_bf<<<aggBlocks, TB>>>(hB, mean);
    k_gemm_bf<<<ggrid, 256, G_SMEM>>>(mean, bw3l, hB, bw3r, b3, hA, 2);
    // layer 4
    k_agg_bf<<<aggBlocks, TB>>>(hA, mean);
    k_gemm_bf<<<ggrid, 256, G_SMEM>>>(mean, bw4l, hA, bw4r, b4, hB, 2);

    // MLP
    k_gemm_bf<<<ggrid, 256, G_SMEM>>>(hB, bwl1, hB, bwl1, bl1, hA, 1);
    k_gemm_bf<<<ggrid, 256, G_SMEM>>>(hA, bwl2, hA, bwl2, bl2, hB, 1);

    // final linear + softmax
    k_last<<<aggBlocks, TB>>>(hB, wlast, blast, out);
}

// round 11
// speedup vs baseline: 1.3043x; 1.0255x over previous
#include <cuda_runtime.h>
#include <cuda_bf16.h>
#include <math.h>
#include <stdint.h>

#define N_NODES 100000
#define NPAD    100096      // multiple of 128
#define NE      1600000
#define HID     256

// ---------------- scratch (device globals: no allocation allowed) ----------------
__device__ __nv_bfloat16 g_hA[(size_t)NPAD * HID];
__device__ __nv_bfloat16 g_hB[(size_t)NPAD * HID];
__device__ __nv_bfloat16 g_mean[(size_t)NPAD * HID];
__device__ __nv_bfloat16 g_wb[8 * HID * HID];   // pre-converted bf16 weights
__device__ float g_h0[NPAD * 3];
__device__ float g_mean0[NPAD * 3];
__device__ int   g_deg[N_NODES];
__device__ int   g_cursor[N_NODES];
__device__ int   g_off[N_NODES + 1];
__device__ unsigned g_csr[NE];                  // byte offsets: src * 512
__device__ float g_part[11 * 64];
__device__ float g_scal[8];
__device__ int   g_i64flag;

// fast tanh: result rounded to bf16 right after, so approx error (~5e-4)
// is below bf16 quantization (~4e-3).
__device__ __forceinline__ float tanhp(float x) {
    float y; asm("tanh.approx.f32 %0, %1;" : "=f"(y) : "f"(x)); return y;
}

// ---------------- init / dtype sniff ----------------
__global__ void k_zero() {
    int i = blockIdx.x * blockDim.x + threadIdx.x;
    if (i < N_NODES) { g_deg[i] = 0; g_cursor[i] = 0; }
    if (i == 0) g_i64flag = 1;
}

__global__ void k_detect(const unsigned int* __restrict__ w) {
    int t = threadIdx.x;
    for (int i = t; i < 1024; i += 256) {
        if (w[2 * i + 1] != 0u) g_i64flag = 0;
    }
}

// ---------------- weight conversion fp32 -> bf16 ----------------
__global__ void k_wconv(const float* w0, const float* w1, const float* w2, const float* w3,
                        const float* w4, const float* w5, const float* w6, const float* w7) {
    const float* ws[8] = {w0, w1, w2, w3, w4, w5, w6, w7};
    int i = blockIdx.x * blockDim.x + threadIdx.x;
    int m = blockIdx.y;
    g_wb[m * (HID * HID) + i] = __float2bfloat16(ws[m][i]);
}

// ---------------- normalize: reductions (warp-shuffle) ----------------
__device__ __forceinline__ float wred(float v, int op) {
    #pragma unroll
    for (int o = 16; o > 0; o >>= 1) {
        float t = __shfl_xor_sync(0xffffffff, v, o);
        v = (op == 0) ? fmaxf(v, t) : (op == 1) ? fminf(v, t) : (v + t);
    }
    return v;
}
__constant__ int c_ops[11] = {0, 1, 0, 1, 2, 2, 0, 0, 2, 2, 0};

__global__ void k_reduce1(const float* __restrict__ x) {
    __shared__ float sh[8][11];
    const float th = 1.5707964f;
    float ct = cosf(th), st = sinf(th);
    float v[11];
    v[0] = -1e30f; v[1] = 1e30f; v[2] = -1e30f; v[3] = 1e30f;
    v[4] = 0.f; v[5] = 0.f; v[6] = -1e30f; v[7] = -1e30f;
    v[8] = 0.f; v[9] = 0.f; v[10] = -1e30f;
    for (int i = blockIdx.x * blockDim.x + threadIdx.x; i < N_NODES; i += gridDim.x * blockDim.x) {
        float cx = x[i * 3 + 0], cy = x[i * 3 + 1], a = x[i * 3 + 2];
        float rx = ct * cx - st * cy, ry = st * cx + ct * cy;
        v[0] = fmaxf(v[0], cx); v[1] = fminf(v[1], cx);
        v[2] = fmaxf(v[2], cy); v[3] = fminf(v[3], cy);
        v[4] += cx; v[5] += cy;
        v[6] = fmaxf(v[6], rx); v[7] = fmaxf(v[7], ry);
        v[8] += rx; v[9] += ry;
        v[10] = fmaxf(v[10], a);
    }
    int warp = threadIdx.x >> 5, lane = threadIdx.x & 31;
    #pragma unroll
    for (int k = 0; k < 11; k++) {
        float r = wred(v[k], c_ops[k]);
        if (lane == 0) sh[warp][k] = r;
    }
    __syncthreads();
    if (threadIdx.x < 11) {
        int k = threadIdx.x, op = c_ops[k];
        float r = sh[0][k];
        #pragma unroll
        for (int w = 1; w < 8; w++) {
            float t = sh[w][k];
            r = (op == 0) ? fmaxf(r, t) : (op == 1) ? fminf(r, t) : (r + t);
        }
        g_part[k * 64 + blockIdx.x] = r;
    }
}

__global__ void k_reduce2() {
    __shared__ float res[11];
    int warp = threadIdx.x >> 5, lane = threadIdx.x & 31;
    if (warp < 11) {
        int op = c_ops[warp];
        float v = (op == 0) ? -1e30f : (op == 1) ? 1e30f : 0.f;
        #pragma unroll
        for (int i = 0; i < 2; i++) {
            float t = g_part[warp * 64 + lane + i * 32];
            v = (op == 0) ? fmaxf(v, t) : (op == 1) ? fminf(v, t) : (v + t);
        }
        v = wred(v, op);
        if (lane == 0) res[warp] = v;
    }
    __syncthreads();
    if (threadIdx.x == 0) {
        bool cond = (res[2] - res[3]) > (res[0] - res[1]);
        float m0 = (cond ? res[8] : res[4]) / (float)N_NODES;
        float m1 = (cond ? res[9] : res[5]) / (float)N_NODES;
        float d0 = cond ? res[6] : res[0];
        float d1 = cond ? res[7] : res[2];
        g_scal[0] = cond ? 1.f : 0.f;
        g_scal[1] = m0; g_scal[2] = m1;
        g_scal[3] = d0; g_scal[4] = d1;
        g_scal[5] = res[10];
    }
}

__global__ void k_normalize(const float* __restrict__ x) {
    int i = blockIdx.x * blockDim.x + threadIdx.x;
    if (i >= N_NODES) return;
    const float th = 1.5707964f;
    float ct = cosf(th), st = sinf(th);
    float cx = x[i * 3 + 0], cy = x[i * 3 + 1], a = x[i * 3 + 2];
    bool cond = g_scal[0] != 0.f;
    float ox = cond ? (ct * cx - st * cy) : cx;
    float oy = cond ? (st * cx + ct * cy) : cy;
    g_h0[i * 3 + 0] = (ox - g_scal[1]) / g_scal[3];
    g_h0[i * 3 + 1] = (oy - g_scal[2]) / g_scal[4];
    g_h0[i * 3 + 2] = a / g_scal[5];
}

// ---------------- CSR build (stores byte offsets src*512) ----------------
__device__ __forceinline__ int edge_at(const void* ei, long long idx) {
    if (g_i64flag) return (int)((const long long*)ei)[idx];
    return ((const int*)ei)[idx];
}

__global__ void k_count(const void* __restrict__ ei) {
    int e = blockIdx.x * blockDim.x + threadIdx.x;
    if (e >= NE) return;
    int dst = edge_at(ei, (long long)NE + e);
    atomicAdd(&g_deg[dst], 1);
}

__global__ void k_scan() {
    __shared__ int sh[1024];
    int tid = threadIdx.x;
    const int per = (N_NODES + 1023) / 1024;
    int start = tid * per;
    int end = start + per; if (end > N_NODES) end = N_NODES; if (start > N_NODES) start = N_NODES;
    int s = 0;
    for (int i = start; i < end; i++) s += g_deg[i];
    sh[tid] = s;
    __syncthreads();
    for (int d = 1; d < 1024; d <<= 1) {
        int v = sh[tid];
        int add = (tid >= d) ? sh[tid - d] : 0;
        __syncthreads();
        sh[tid] = v + add;
        __syncthreads();
    }
    int run = sh[tid] - s;
    for (int i = start; i < end; i++) { g_off[i] = run; run += g_deg[i]; }
    if (tid == 0) g_off[N_NODES] = NE;
}

__global__ void k_fill(const void* __restrict__ ei) {
    int e = blockIdx.x * blockDim.x + threadIdx.x;
    if (e >= NE) return;
    int src = edge_at(ei, e);
    int dst = edge_at(ei, (long long)NE + e);
    int p = atomicAdd(&g_cursor[dst], 1);
    g_csr[g_off[dst] + p] = ((unsigned)src) << 9;   // byte offset into 512B rows
}

// ---------------- layer 1 (3-dim features) ----------------
__global__ void k_agg1() {
    int i = blockIdx.x * blockDim.x + threadIdx.x;
    if (i >= N_NODES) return;
    int s = g_off[i], e = g_off[i + 1];
    float a0 = 0.f, a1 = 0.f, a2 = 0.f;
    for (int p = s; p < e; p++) {
        int src = (int)(g_csr[p] >> 9);
        a0 += g_h0[src * 3 + 0];
        a1 += g_h0[src * 3 + 1];
        a2 += g_h0[src * 3 + 2];
    }
    float inv = 1.f / fmaxf((float)(e - s), 1.f);
    g_mean0[i * 3 + 0] = a0 * inv;
    g_mean0[i * 3 + 1] = a1 * inv;
    g_mean0[i * 3 + 2] = a2 * inv;
}

__global__ void k_dense1(const float* __restrict__ w1l, const float* __restrict__ b1,
                         const float* __restrict__ w1r) {
    int t = blockIdx.x * blockDim.x + threadIdx.x;
    if (t >= N_NODES * HID) return;
    int i = t >> 8, j = t & 255;
    float acc = b1[j];
    #pragma unroll
    for (int k = 0; k < 3; k++)
        acc += g_mean0[i * 3 + k] * w1l[k * HID + j] + g_h0[i * 3 + k] * w1r[k * HID + j];
    g_hA[(size_t)i * HID + j] = __float2bfloat16(tanhp(acc));
}

// ---------------- mean aggregation: warp/node, pairwise bf16 add + fp32 acc ----------------
__global__ void k_agg_bf(const __nv_bfloat16* __restrict__ h, __nv_bfloat16* __restrict__ mean) {
    int gw = (blockIdx.x * blockDim.x + threadIdx.x) >> 5;
    int lane = threadIdx.x & 31;
    if (gw >= N_NODES) return;
    int s = g_off[gw], e = g_off[gw + 1];
    const char* hb = (const char*)h;
    int laneOff = lane * 16;
    float acc[8];
    #pragma unroll
    for (int j = 0; j < 8; j++) acc[j] = 0.f;

    int p = s;
    for (; p + 4 <= e; p += 4) {
        unsigned o0 = g_csr[p], o1 = g_csr[p + 1], o2 = g_csr[p + 2], o3 = g_csr[p + 3];
        uint4 v0 = *(const uint4*)(hb + o0 + laneOff);
        uint4 v1 = *(const uint4*)(hb + o1 + laneOff);
        uint4 v2 = *(const uint4*)(hb + o2 + laneOff);
        uint4 v3 = *(const uint4*)(hb + o3 + laneOff);
        const __nv_bfloat162* a0 = (const __nv_bfloat162*)&v0;
        const __nv_bfloat162* a1 = (const __nv_bfloat162*)&v1;
        const __nv_bfloat162* a2 = (const __nv_bfloat162*)&v2;
        const __nv_bfloat162* a3 = (const __nv_bfloat162*)&v3;
        #pragma unroll
        for (int j = 0; j < 4; j++) {
            __nv_bfloat162 s01 = __hadd2(a0[j], a1[j]);
            __nv_bfloat162 s23 = __hadd2(a2[j], a3[j]);
            float2 f01 = __bfloat1622float2(s01);
            float2 f23 = __bfloat1622float2(s23);
            acc[2 * j]     += f01.x + f23.x;
            acc[2 * j + 1] += f01.y + f23.y;
        }
    }
    if (p + 2 <= e) {
        unsigned o0 = g_csr[p], o1 = g_csr[p + 1];
        uint4 v0 = *(const uint4*)(hb + o0 + laneOff);
        uint4 v1 = *(const uint4*)(hb + o1 + laneOff);
        const __nv_bfloat162* a0 = (const __nv_bfloat162*)&v0;
        const __nv_bfloat162* a1 = (const __nv_bfloat162*)&v1;
        #pragma unroll
        for (int j = 0; j < 4; j++) {
            float2 f = __bfloat1622float2(__hadd2(a0[j], a1[j]));
            acc[2 * j]     += f.x;
            acc[2 * j + 1] += f.y;
        }
        p += 2;
    }
    if (p < e) {
        uint4 v = *(const uint4*)(hb + g_csr[p] + laneOff);
        const __nv_bfloat162* a = (const __nv_bfloat162*)&v;
        #pragma unroll
        for (int j = 0; j < 4; j++) {
            float2 f = __bfloat1622float2(a[j]);
            acc[2 * j]     += f.x;
            acc[2 * j + 1] += f.y;
        }
    }
    float inv = 1.f / fmaxf((float)(e - s), 1.f);
    uint4 o;
    __nv_bfloat162* po = (__nv_bfloat162*)&o;
    #pragma unroll
    for (int j = 0; j < 4; j++)
        po[j] = __float22bfloat162_rn(make_float2(acc[2 * j] * inv, acc[2 * j + 1] * inv));
    ((uint4*)(mean + (size_t)gw * HID))[lane] = o;
}

// ---------------- bf16 tensor-core fused dual-GEMM + bias + tanh (R6 config) ----------------
__device__ __forceinline__ uint32_t smem_u32(const void* p) {
    return (uint32_t)__cvta_generic_to_shared(p);
}

#define GA_STRIDE 72
#define GB_STRIDE 136
#define GA_BYTES  (128 * GA_STRIDE * 2)           // 18432 per buffer
#define GB_BYTES  (64 * GB_STRIDE * 2)            // 17408 per buffer
#define G_SMEM    (2 * GA_BYTES + 2 * GB_BYTES)   // 71680

__global__ void __launch_bounds__(256) k_gemm_bf(
    const __nv_bfloat16* __restrict__ A0, const __nv_bfloat16* __restrict__ B0,
    const __nv_bfloat16* __restrict__ A1, const __nv_bfloat16* __restrict__ B1,
    const float* __restrict__ bias, __nv_bfloat16* __restrict__ out, int nA)
{
    extern __shared__ __align__(16) char sm[];
    __nv_bfloat16* Asm = (__nv_bfloat16*)sm;
    __nv_bfloat16* Bsm = (__nv_bfloat16*)(sm + 2 * GA_BYTES);

    int tid  = threadIdx.x;
    int lane = tid & 31;
    int warp = tid >> 5;
    int warpRow = warp >> 2;
    int warpCol = warp & 3;
    int quad = lane >> 2;
    int tq   = lane & 3;

    int rowBase = blockIdx.x * 128;
    int colBase = blockIdx.y * 128;

    float acc[4][4][4];
    #pragma unroll
    for (int mi = 0; mi < 4; mi++)
        #pragma unroll
        for (int ni = 0; ni < 4; ni++)
            #pragma unroll
            for (int c = 0; c < 4; c++) acc[mi][ni][c] = 0.f;

    const int iters = nA * 4;

    auto issue = [&](int it, int buf) {
        int pass = it >> 2;
        int k0 = (it & 3) * 64;
        const __nv_bfloat16* A = pass ? A1 : A0;
        const __nv_bfloat16* B = pass ? B1 : B0;
        __nv_bfloat16* Ab = Asm + buf * (GA_BYTES / 2);
        __nv_bfloat16* Bb = Bsm + buf * (GB_BYTES / 2);
        #pragma unroll
        for (int i = 0; i < 4; i++) {
            int s = tid + i * 256;
            int row = s >> 3, seg = s & 7;
            const void* src = A + (size_t)(rowBase + row) * 256 + k0 + seg * 8;
            uint32_t dst = smem_u32(Ab + row * GA_STRIDE + seg * 8);
            asm volatile("cp.async.ca.shared.global [%0], [%1], 16;\n" :: "r"(dst), "l"(src));
        }
        #pragma unroll
        for (int i = 0; i < 4; i++) {
            int s = tid + i * 256;
            int row = s >> 4, seg = s & 15;
            const void* src = B + (size_t)(k0 + row) * 256 + colBase + seg * 8;
            uint32_t dst = smem_u32(Bb + row * GB_STRIDE + seg * 8);
            asm volatile("cp.async.ca.shared.global [%0], [%1], 16;\n" :: "r"(dst), "l"(src));
        }
        asm volatile("cp.async.commit_group;\n");
    };

    issue(0, 0);
    for (int it = 0; it < iters; it++) {
        int buf = it & 1;
        if (it + 1 < iters) {
            issue(it + 1, buf ^ 1);
            asm volatile("cp.async.wait_group 1;\n");
        } else {
            asm volatile("cp.async.wait_group 0;\n");
        }
        __syncthreads();

        __nv_bfloat16* Ab = Asm + buf * (GA_BYTES / 2);
        __nv_bfloat16* Bb = Bsm + buf * (GB_BYTES / 2);
        #pragma unroll
        for (int kk = 0; kk < 64; kk += 16) {
            uint32_t af[4][4];
            uint32_t bf[4][2];
            #pragma unroll
            for (int mi = 0; mi < 4; mi++) {
                int r0 = warpRow * 64 + mi * 16;
                uint32_t addr = smem_u32(Ab + (r0 + (lane & 15)) * GA_STRIDE + kk + (lane >> 4) * 8);
                asm volatile("ldmatrix.sync.aligned.m8n8.x4.shared.b16 {%0,%1,%2,%3}, [%4];"
                             : "=r"(af[mi][0]), "=r"(af[mi][1]), "=r"(af[mi][2]), "=r"(af[mi][3])
                             : "r"(addr));
            }
            #pragma unroll
            for (int nb = 0; nb < 2; nb++) {
                int n0 = warpCol * 32 + nb * 16;
                uint32_t addr = smem_u32(Bb + (kk + (lane & 15)) * GB_STRIDE + n0 + (lane >> 4) * 8);
                asm volatile("ldmatrix.sync.aligned.m8n8.x4.trans.shared.b16 {%0,%1,%2,%3}, [%4];"
                             : "=r"(bf[nb * 2][0]), "=r"(bf[nb * 2][1]),
                               "=r"(bf[nb * 2 + 1][0]), "=r"(bf[nb * 2 + 1][1])
                             : "r"(addr));
            }
            #pragma unroll
            for (int mi = 0; mi < 4; mi++)
                #pragma unroll
                for (int ni = 0; ni < 4; ni++) {
                    asm volatile(
                        "mma.sync.aligned.m16n8k16.row.col.f32.bf16.bf16.f32 "
                        "{%0,%1,%2,%3}, {%4,%5,%6,%7}, {%8,%9}, {%0,%1,%2,%3};"
                        : "+f"(acc[mi][ni][0]), "+f"(acc[mi][ni][1]),
                          "+f"(acc[mi][ni][2]), "+f"(acc[mi][ni][3])
                        : "r"(af[mi][0]), "r"(af[mi][1]), "r"(af[mi][2]), "r"(af[mi][3]),
                          "r"(bf[ni][0]), "r"(bf[ni][1]));
                }
        }
        __syncthreads();
    }

    // epilogue: bias + tanh.approx, bf16 out
    #pragma unroll
    for (int ni = 0; ni < 4; ni++) {
        int col = colBase + warpCol * 32 + ni * 8 + tq * 2;
        float b0 = bias[col], b1 = bias[col + 1];
        #pragma unroll
        for (int mi = 0; mi < 4; mi++) {
            int r0 = rowBase + warpRow * 64 + mi * 16 + quad;
            if (r0 < N_NODES) {
                __nv_bfloat162 v = __float22bfloat162_rn(
                    make_float2(tanhp(acc[mi][ni][0] + b0), tanhp(acc[mi][ni][1] + b1)));
                *(__nv_bfloat162*)(out + (size_t)r0 * 256 + col) = v;
            }
            int r1 = r0 + 8;
            if (r1 < N_NODES) {
                __nv_bfloat162 v = __float22bfloat162_rn(
                    make_float2(tanhp(acc[mi][ni][2] + b0), tanhp(acc[mi][ni][3] + b1)));
                *(__nv_bfloat162*)(out + (size_t)r1 * 256 + col) = v;
            }
        }
    }
}

// ---------------- final projection (256->4) + softmax, warp per node ----------------
__global__ void k_last(const __nv_bfloat16* __restrict__ h, const float* __restrict__ wlast,
                       const float* __restrict__ blast, float* __restrict__ out) {
    int gw = (blockIdx.x * blockDim.x + threadIdx.x) >> 5;
    int lane = threadIdx.x & 31;
    if (gw >= N_NODES) return;
    uint4 v = ((const uint4*)(h + (size_t)gw * 256))[lane];
    const __nv_bfloat162* pv = (const __nv_bfloat162*)&v;
    float hv[8];
    #pragma unroll
    for (int j = 0; j < 4; j++) {
        float2 f = __bfloat1622float2(pv[j]);
        hv[2 * j] = f.x;
        hv[2 * j + 1] = f.y;
    }
    float acc0 = 0.f, acc1 = 0.f, acc2 = 0.f, acc3 = 0.f;
    #pragma unroll
    for (int t = 0; t < 8; t++) {
        int k = lane * 8 + t;
        float4 wl = ((const float4*)wlast)[k];
        acc0 += hv[t] * wl.x;
        acc1 += hv[t] * wl.y;
        acc2 += hv[t] * wl.z;
        acc3 += hv[t] * wl.w;
    }
    #pragma unroll
    for (int o = 16; o > 0; o >>= 1) {
        acc0 += __shfl_xor_sync(0xffffffff, acc0, o);
        acc1 += __shfl_xor_sync(0xffffffff, acc1, o);
        acc2 += __shfl_xor_sync(0xffffffff, acc2, o);
        acc3 += __shfl_xor_sync(0xffffffff, acc3, o);
    }
    if (lane == 0) {
        float l0 = acc0 + blast[0], l1 = acc1 + blast[1];
        float l2 = acc2 + blast[2], l3 = acc3 + blast[3];
        float m = fmaxf(fmaxf(l0, l1), fmaxf(l2, l3));
        float e0 = expf(l0 - m), e1 = expf(l1 - m), e2 = expf(l2 - m), e3 = expf(l3 - m);
        float s = e0 + e1 + e2 + e3;
        out[gw * 4 + 0] = e0 / s;
        out[gw * 4 + 1] = e1 / s;
        out[gw * 4 + 2] = e2 / s;
        out[gw * 4 + 3] = e3 / s;
    }
}

// ---------------- host ----------------
extern "C" void kernel_launch(void* const* d_in, const int* in_sizes, int n_in,
                              void* d_out, int out_size) {
    const float* x    = (const float*)d_in[0];
    const void*  ei   = d_in[1];
    const float* w1l  = (const float*)d_in[2];
    const float* b1   = (const float*)d_in[3];
    const float* w1r  = (const float*)d_in[4];
    const float* w2l  = (const float*)d_in[5];
    const float* b2   = (const float*)d_in[6];
    const float* w2r  = (const float*)d_in[7];
    const float* w3l  = (const float*)d_in[8];
    const float* b3   = (const float*)d_in[9];
    const float* w3r  = (const float*)d_in[10];
    const float* w4l  = (const float*)d_in[11];
    const float* b4   = (const float*)d_in[12];
    const float* w4r  = (const float*)d_in[13];
    const float* wl1  = (const float*)d_in[14];
    const float* bl1  = (const float*)d_in[15];
    const float* wl2  = (const float*)d_in[16];
    const float* bl2  = (const float*)d_in[17];
    const float* wlast = (const float*)d_in[18];
    const float* blast = (const float*)d_in[19];
    float* out = (float*)d_out;

    static __nv_bfloat16 *hA = nullptr, *hB = nullptr, *mean = nullptr, *wb = nullptr;
    if (!hA) {
        cudaGetSymbolAddress((void**)&hA, g_hA);
        cudaGetSymbolAddress((void**)&hB, g_hB);
        cudaGetSymbolAddress((void**)&mean, g_mean);
        cudaGetSymbolAddress((void**)&wb, g_wb);
        cudaFuncSetAttribute(k_gemm_bf, cudaFuncAttributeMaxDynamicSharedMemorySize, G_SMEM);
    }
    const int WSZ = HID * HID;
    const __nv_bfloat16* bw2l = wb + 0 * WSZ;
    const __nv_bfloat16* bw2r = wb + 1 * WSZ;
    const __nv_bfloat16* bw3l = wb + 2 * WSZ;
    const __nv_bfloat16* bw3r = wb + 3 * WSZ;
    const __nv_bfloat16* bw4l = wb + 4 * WSZ;
    const __nv_bfloat16* bw4r = wb + 5 * WSZ;
    const __nv_bfloat16* bwl1 = wb + 6 * WSZ;
    const __nv_bfloat16* bwl2 = wb + 7 * WSZ;

    const int TB = 256;
    const int aggBlocks = (N_NODES * 32 + TB - 1) / TB;
    dim3 ggrid(NPAD / 128, 2);

    k_zero<<<(N_NODES + TB - 1) / TB, TB>>>();
    k_detect<<<1, 256>>>((const unsigned int*)ei);
    k_wconv<<<dim3(WSZ / TB, 8), TB>>>(w2l, w2r, w3l, w3r, w4l, w4r, wl1, wl2);
    k_reduce1<<<64, 256>>>(x);
    k_reduce2<<<1, 352>>>();
    k_normalize<<<(N_NODES + TB - 1) / TB, TB>>>(x);
    k_count<<<(NE + TB - 1) / TB, TB>>>(ei);
    k_scan<<<1, 1024>>>();
    k_fill<<<(NE + TB - 1) / TB, TB>>>(ei);

    // layer 1 (K=3)
    k_agg1<<<(N_NODES + TB - 1) / TB, TB>>>();
    k_dense1<<<(N_NODES * HID + TB - 1) / TB, TB>>>(w1l, b1, w1r);

    // layer 2
    k_agg_bf<<<aggBlocks, TB>>>(hA, mean);
    k_gemm_bf<<<ggrid, 256, G_SMEM>>>(mean, bw2l, hA, bw2r, b2, hB, 2);
    // layer 3
    k_agg_bf<<<aggBlocks, TB>>>(hB, mean);
    k_gemm_bf<<<ggrid, 256, G_SMEM>>>(mean, bw3l, hB, bw3r, b3, hA, 2);
    // layer 4
    k_agg_bf<<<aggBlocks, TB>>>(hA, mean);
    k_gemm_bf<<<ggrid, 256, G_SMEM>>>(mean, bw4l, hA, bw4r, b4, hB, 2);

    // MLP
    k_gemm_bf<<<ggrid, 256, G_SMEM>>>(hB, bwl1, hB, bwl1, bl1, hA, 1);
    k_gemm_bf<<<ggrid, 256, G_SMEM>>>(hA, bwl2, hA, bwl2, bl2, hB, 1);

    // final linear + softmax
    k_last<<<aggBlocks, TB>>>(hB, wlast, blast, out);
}